// round 3
// baseline (speedup 1.0000x reference)
#include <cuda_runtime.h>
#include <cstdint>
#include <cstddef>

#define BATCH 4096
#define DIN   8192
#define DOUT  8192
#define BB    128
#define KIN   64
#define KOUT  64
#define NF    65     // rfft bins of 128

// ---------------- scratch (static device globals; no allocation) -------------
__device__ float g_Xre[NF][BATCH * KIN];            // 68 MB
__device__ float g_Xim[NF][BATCH * KIN];            // 68 MB
__device__ float g_Wre[NF][KIN * KOUT];             // [f][j*64+o], conj(fft(W)) re
__device__ float g_Wim[NF][KIN * KOUT];             // [f][j*64+o], conj(fft(W)) im
__device__ float g_Y[(size_t)BATCH * NF * KOUT * 2]; // [b][f][o][re,im], 136 MB

// ---------------- warp-level 128-pt radix-2 DIF FFT --------------------------
// Layout: lane holds points n = r*32 + lane, r = 0..3. Natural-order input,
// bit-reversed output: y[n] = X[brev7(n)]. Twiddles tw[m] = e^{-2*pi*i*m/128}.
__device__ __forceinline__ void fft128(float xr[4], float xi[4],
                                       const float* __restrict__ twc,
                                       const float* __restrict__ tws,
                                       int lane) {
    // stage h = 64 : pairs (r, r+2), twiddle index i = r*32+lane
#pragma unroll
    for (int r = 0; r < 2; r++) {
        int i = r * 32 + lane;
        float ar = xr[r], ai = xi[r], br = xr[r + 2], bi = xi[r + 2];
        xr[r] = ar + br; xi[r] = ai + bi;
        float dr = ar - br, di = ai - bi;
        float c = twc[i], s = tws[i];
        xr[r + 2] = dr * c - di * s;
        xi[r + 2] = dr * s + di * c;
    }
    // stage h = 32 : pairs (0,1) and (2,3), twiddle W64^lane = W128^(2*lane)
    {
        float c = twc[2 * lane], s = tws[2 * lane];
#pragma unroll
        for (int p = 0; p < 2; p++) {
            int a = 2 * p, bq = 2 * p + 1;
            float ar = xr[a], ai = xi[a], br = xr[bq], bi = xi[bq];
            xr[a] = ar + br; xi[a] = ai + bi;
            float dr = ar - br, di = ai - bi;
            xr[bq] = dr * c - di * s;
            xi[bq] = dr * s + di * c;
        }
    }
    // stages h = 16, 8, 4, 2, 1 : cross-lane butterflies
#pragma unroll
    for (int h = 16; h >= 1; h >>= 1) {
        int m = (lane & (h - 1)) * (64 / h);
        float c = twc[m], s = tws[m];
        bool upper = (lane & h) != 0;
#pragma unroll
        for (int r = 0; r < 4; r++) {
            float pr = __shfl_xor_sync(0xffffffffu, xr[r], h);
            float pi = __shfl_xor_sync(0xffffffffu, xi[r], h);
            float ur = upper ? pr : xr[r];
            float ui = upper ? pi : xi[r];
            float vr = upper ? xr[r] : pr;
            float vi = upper ? xi[r] : pi;
            if (!upper) { xr[r] = ur + vr; xi[r] = ui + vi; }
            else {
                float dr = ur - vr, di = ui - vi;
                xr[r] = dr * c - di * s;
                xi[r] = dr * s + di * c;
            }
        }
    }
}

// ---------------- K0: conj(FFT) of weight first-rows (direct DFT, tiny) ------
__global__ void wfft_kernel(const float* __restrict__ W) {
    __shared__ float sw[128];
    __shared__ float tc[128];
    __shared__ float ts[128];
    int oj = blockIdx.x;            // o*64 + j
    int t = threadIdx.x;            // 0..127
    sw[t] = W[oj * 128 + t];
    float ang = 6.2831853071795864769f * (float)t / 128.0f;  // +sin => conj
    tc[t] = cosf(ang);
    ts[t] = sinf(ang);
    __syncthreads();
    if (t < NF) {
        float ar = 0.f, ai = 0.f;
#pragma unroll 8
        for (int u = 0; u < 128; u++) {
            int p = (t * u) & 127;
            ar = fmaf(sw[u], tc[p], ar);
            ai = fmaf(sw[u], ts[p], ai);
        }
        int o = oj >> 6, j = oj & 63;
        g_Wre[t][j * 64 + o] = ar;   // transposed [j][o] for conflict-free LDS
        g_Wim[t][j * 64 + o] = ai;
    }
}

// ---------------- K1: FFT of all x blocks -------------------------------------
// One CTA per batch row b, 512 threads (16 warps x 4 blocks each).
__global__ void xfft_kernel(const float* __restrict__ x,
                            const float* __restrict__ D) {
    extern __shared__ float sm[];
    float* sx  = sm;                        // 8192
    float* sXr = sm + 8192;                 // 65*65 (pitch 65: anti-conflict)
    float* sXi = sXr + 65 * 65;             // 65*65
    float* twc = sXi + 65 * 65;             // 64
    float* tws = twc + 64;                  // 64
    int b = blockIdx.x, tid = threadIdx.x;
    if (tid < 64) {
        float ang = -6.2831853071795864769f * (float)tid / 128.0f;
        twc[tid] = cosf(ang);
        tws[tid] = sinf(ang);
    }
    const float* xb = x + (size_t)b * DIN;
    for (int i = tid; i < DIN; i += 512) sx[i] = xb[i] * D[i];
    __syncthreads();

    int warp = tid >> 5, lane = tid & 31;
    for (int jj = 0; jj < 4; jj++) {
        int j = warp * 4 + jj;
        float xr[4], xi[4];
#pragma unroll
        for (int r = 0; r < 4; r++) { xr[r] = sx[j * 128 + r * 32 + lane]; xi[r] = 0.f; }
        fft128(xr, xi, twc, tws, lane);
#pragma unroll
        for (int r = 0; r < 4; r++) {
            int n = r * 32 + lane;
            int k = __brev((unsigned)n) >> 25;   // brev7
            if (k < NF) { sXr[k * 65 + j] = xr[r]; sXi[k * 65 + j] = xi[r]; }
        }
    }
    __syncthreads();
    // coalesced plane flush: 64 contiguous floats per frequency
    for (int i = tid; i < NF * KIN; i += 512) {
        int f = i >> 6, j = i & 63;
        g_Xre[f][b * 64 + j] = sXr[f * 65 + j];
        g_Xim[f][b * 64 + j] = sXi[f * 65 + j];
    }
}

// ---------------- K2: 65 per-frequency complex GEMMs (fp32 FMA) ---------------
// CTA = (b-tile of 128 rows, one frequency). 256 threads, each 8b x 4o outputs.
__global__ void __launch_bounds__(256) cgemm_kernel() {
    extern __shared__ float sm[];
    float* sXr = sm;                 // 128 * 65 (pitch 65)
    float* sXi = sXr + 128 * 65;
    float* sWr = sXi + 128 * 65;     // 64*64 [j][o]
    float* sWi = sWr + 4096;
    int f = blockIdx.y, bt = blockIdx.x, tid = threadIdx.x;

    const float* gxr = g_Xre[f] + bt * 128 * 64;
    const float* gxi = g_Xim[f] + bt * 128 * 64;
    for (int i = tid; i < 8192; i += 256) {
        int bl = i >> 6, j = i & 63;
        sXr[bl * 65 + j] = gxr[i];
        sXi[bl * 65 + j] = gxi[i];
    }
    for (int i = tid; i < 4096; i += 256) {
        sWr[i] = g_Wre[f][i];
        sWi[i] = g_Wim[f][i];
    }
    __syncthreads();

    int ow = tid & 15, bw = tid >> 4;
    float accR[8][4], accI[8][4];
#pragma unroll
    for (int rr = 0; rr < 8; rr++)
#pragma unroll
        for (int c = 0; c < 4; c++) { accR[rr][c] = 0.f; accI[rr][c] = 0.f; }

    const float* xrp = sXr + bw * 8 * 65;
    const float* xip = sXi + bw * 8 * 65;
#pragma unroll 4
    for (int j = 0; j < 64; j++) {
        float wr[4], wi[4];
#pragma unroll
        for (int c = 0; c < 4; c++) {
            wr[c] = sWr[j * 64 + ow + 16 * c];
            wi[c] = sWi[j * 64 + ow + 16 * c];
        }
#pragma unroll
        for (int rr = 0; rr < 8; rr++) {
            float xr = xrp[rr * 65 + j];
            float xi = xip[rr * 65 + j];
#pragma unroll
            for (int c = 0; c < 4; c++) {
                // Y = X * conj(W):  Yr = Xr*A - Xi*B ; Yi = Xr*B + Xi*A
                accR[rr][c] = fmaf(xr,  wr[c], accR[rr][c]);
                accR[rr][c] = fmaf(-xi, wi[c], accR[rr][c]);
                accI[rr][c] = fmaf(xr,  wi[c], accI[rr][c]);
                accI[rr][c] = fmaf(xi,  wr[c], accI[rr][c]);
            }
        }
    }
    // write Y[b][f][o] as float2 (re, im) — contiguous across o
#pragma unroll
    for (int rr = 0; rr < 8; rr++) {
        int b = bt * 128 + bw * 8 + rr;
        float2* dst = reinterpret_cast<float2*>(g_Y + ((size_t)b * NF + f) * (KOUT * 2));
#pragma unroll
        for (int c = 0; c < 4; c++) {
            int o = ow + 16 * c;
            dst[o] = make_float2(accR[rr][c], accI[rr][c]);
        }
    }
}

// ---------------- K3: Hermitian inverse FFT + write output --------------------
// One CTA per batch row b; 512 threads; warp handles 4 output blocks.
// Real IFFT: y[t] = Re( FFT_fwd( conj(Yfull) ) )[t] / 128.
__global__ void ifft_kernel(float* __restrict__ out) {
    __shared__ float sYr[KOUT * 65];     // [o][f], pitch 65
    __shared__ float sYi[KOUT * 65];
    __shared__ float twc[64];
    __shared__ float tws[64];
    __shared__ float stage[16 * 128];
    int b = blockIdx.x, tid = threadIdx.x;
    if (tid < 64) {
        float ang = -6.2831853071795864769f * (float)tid / 128.0f;
        twc[tid] = cosf(ang);
        tws[tid] = sinf(ang);
    }
    const float* gy = g_Y + (size_t)b * (NF * KOUT * 2);
    for (int i = tid; i < NF * KOUT * 2; i += 512) {   // contiguous 33 KB load
        int f = i >> 7;
        int rem = i & 127;
        int o = rem >> 1, c = rem & 1;
        float v = gy[i];
        if (c == 0) sYr[o * 65 + f] = v;
        else        sYi[o * 65 + f] = v;
    }
    __syncthreads();

    int warp = tid >> 5, lane = tid & 31;
    float* st = stage + warp * 128;
    for (int oo = 0; oo < 4; oo++) {
        int o = warp * 4 + oo;
        float xr[4], xi[4];
#pragma unroll
        for (int r = 0; r < 4; r++) {
            int k = r * 32 + lane;
            if (k <= 64) {                       // z[k] = conj(Y[k])
                xr[r] =  sYr[o * 65 + k];
                xi[r] = -sYi[o * 65 + k];
            } else {                             // z[k] = conj(conj(Y[128-k])) = Y[128-k]
                int k2 = 128 - k;
                xr[r] = sYr[o * 65 + k2];
                xi[r] = sYi[o * 65 + k2];
            }
        }
        fft128(xr, xi, twc, tws, lane);
#pragma unroll
        for (int r = 0; r < 4; r++) {
            int n = r * 32 + lane;
            int tpos = __brev((unsigned)n) >> 25;
            st[tpos] = xr[r] * (1.0f / 128.0f);
        }
        __syncwarp();
#pragma unroll
        for (int r = 0; r < 4; r++)
            out[(size_t)b * DOUT + o * 128 + r * 32 + lane] = st[r * 32 + lane];
        __syncwarp();
    }
}

// ---------------- launch ------------------------------------------------------
extern "C" void kernel_launch(void* const* d_in, const int* in_sizes, int n_in,
                              void* d_out, int out_size) {
    const float* x = (const float*)d_in[0];   // (4096, 8192)
    const float* W = (const float*)d_in[1];   // (64, 64, 128)
    const float* D = (const float*)d_in[2];   // (8192,)
    float* out = (float*)d_out;               // (4096, 8192)

    (void)in_sizes; (void)n_in; (void)out_size;

    const int smem_x = (8192 + 2 * 65 * 65 + 128) * 4;          // 67080 B
    const int smem_g = (2 * 128 * 65 + 2 * 64 * 64) * 4;        // 99328 B
    cudaFuncSetAttribute(xfft_kernel,  cudaFuncAttributeMaxDynamicSharedMemorySize, smem_x);
    cudaFuncSetAttribute(cgemm_kernel, cudaFuncAttributeMaxDynamicSharedMemorySize, smem_g);

    wfft_kernel<<<KOUT * KIN, 128>>>(W);
    xfft_kernel<<<BATCH, 512, smem_x>>>(x, D);
    cgemm_kernel<<<dim3(BATCH / 128, NF), 256, smem_g>>>();
    ifft_kernel<<<BATCH, 512>>>(out);
}

// round 5
// speedup vs baseline: 1.1125x; 1.1125x over previous
#include <cuda_runtime.h>
#include <cstdint>
#include <cstddef>

typedef unsigned long long ull;

#define BATCH 4096
#define DIN   8192
#define DOUT  8192
#define KIN   64
#define KOUT  64
#define NF    65     // rfft bins of 128

#define FMA2(d, a, b, c) \
    asm("fma.rn.f32x2 %0, %1, %2, %3;" : "=l"(d) : "l"(a), "l"(b), "l"(c))
#define UNPACK2(lo, hi, v) \
    asm("mov.b64 {%0, %1}, %2;" : "=f"(lo), "=f"(hi) : "l"(v))

// ---------------- scratch (static device globals; no allocation) -------------
__device__ float g_Xre[NF][BATCH * KIN];             // [f][b*64+j]
__device__ float g_Xim[NF][BATCH * KIN];
__device__ float g_Wre[NF][KIN * KOUT];              // [f][j*64+o] = Re conj(fft W)
__device__ float g_Wim[NF][KIN * KOUT];              // [f][j*64+o] = Im conj(fft W)
__device__ float g_Y[(size_t)BATCH * NF * KOUT * 2]; // [b][f][o][re,im]

// ---------------- warp-level 128-pt radix-2 DIF FFT --------------------------
// Lane holds points n = r*32 + lane. Natural input, bit-reversed output:
// slot n ends up holding X[brev7(n)].
__device__ __forceinline__ void fft128(float xr[4], float xi[4],
                                       const float* __restrict__ twc,
                                       const float* __restrict__ tws,
                                       int lane) {
#pragma unroll
    for (int r = 0; r < 2; r++) {
        int i = r * 32 + lane;
        float ar = xr[r], ai = xi[r], br = xr[r + 2], bi = xi[r + 2];
        xr[r] = ar + br; xi[r] = ai + bi;
        float dr = ar - br, di = ai - bi;
        float c = twc[i], s = tws[i];
        xr[r + 2] = dr * c - di * s;
        xi[r + 2] = dr * s + di * c;
    }
    {
        float c = twc[2 * lane], s = tws[2 * lane];
#pragma unroll
        for (int p = 0; p < 2; p++) {
            int a = 2 * p, bq = 2 * p + 1;
            float ar = xr[a], ai = xi[a], br = xr[bq], bi = xi[bq];
            xr[a] = ar + br; xi[a] = ai + bi;
            float dr = ar - br, di = ai - bi;
            xr[bq] = dr * c - di * s;
            xi[bq] = dr * s + di * c;
        }
    }
#pragma unroll
    for (int h = 16; h >= 1; h >>= 1) {
        int m = (lane & (h - 1)) * (64 / h);
        float c = twc[m], s = tws[m];
        bool upper = (lane & h) != 0;
#pragma unroll
        for (int r = 0; r < 4; r++) {
            float pr = __shfl_xor_sync(0xffffffffu, xr[r], h);
            float pi = __shfl_xor_sync(0xffffffffu, xi[r], h);
            float ur = upper ? pr : xr[r];
            float ui = upper ? pi : xi[r];
            float vr = upper ? xr[r] : pr;
            float vi = upper ? xi[r] : pi;
            if (!upper) { xr[r] = ur + vr; xi[r] = ui + vi; }
            else {
                float dr = ur - vr, di = ui - vi;
                xr[r] = dr * c - di * s;
                xi[r] = dr * s + di * c;
            }
        }
    }
}

// ---------------- K0: conj(FFT) of weight first-rows (direct DFT, tiny) ------
__global__ void wfft_kernel(const float* __restrict__ W) {
    __shared__ float sw[128];
    __shared__ float tc[128];
    __shared__ float ts[128];
    int oj = blockIdx.x;            // o*64 + j
    int t = threadIdx.x;            // 0..127
    sw[t] = W[oj * 128 + t];
    float ang = 6.2831853071795864769f * (float)t / 128.0f;  // +sin => conj
    tc[t] = cosf(ang);
    ts[t] = sinf(ang);
    __syncthreads();
    if (t < NF) {
        float ar = 0.f, ai = 0.f;
#pragma unroll 8
        for (int u = 0; u < 128; u++) {
            int p = (t * u) & 127;
            ar = fmaf(sw[u], tc[p], ar);
            ai = fmaf(sw[u], ts[p], ai);
        }
        int o = oj >> 6, j = oj & 63;
        g_Wre[t][j * 64 + o] = ar;
        g_Wim[t][j * 64 + o] = ai;
    }
}

// ---------------- K1: FFT of x blocks, 2 real blocks per complex FFT ----------
// One CTA per batch row b, 512 threads. Warp w handles pairs 2w, 2w+1
// (pair p = blocks 2p, 2p+1). Z stored in natural slot order (slot n holds
// Z[brev7(n)]), pitch 33 => conflict-free STS.
__global__ void __launch_bounds__(512) xfft_kernel(const float* __restrict__ x,
                                                   const float* __restrict__ D) {
    extern __shared__ float sm[];
    float* sZr = sm;                 // [128][33]
    float* sZi = sZr + 128 * 33;
    float* twc = sZi + 128 * 33;
    float* tws = twc + 64;
    int b = blockIdx.x, tid = threadIdx.x;
    if (tid < 64) {
        float ang = -6.2831853071795864769f * (float)tid / 128.0f;
        twc[tid] = cosf(ang);
        tws[tid] = sinf(ang);
    }
    __syncthreads();
    int warp = tid >> 5, lane = tid & 31;
    const float* xb = x + (size_t)b * DIN;
    for (int pp = 0; pp < 2; pp++) {
        int p = warp * 2 + pp;                 // pair 0..31 -> blocks 2p, 2p+1
        float xr[4], xi[4];
#pragma unroll
        for (int r = 0; r < 4; r++) {
            int n = r * 32 + lane;
            int iu = (2 * p) * 128 + n;
            int iv = iu + 128;
            xr[r] = xb[iu] * D[iu];
            xi[r] = xb[iv] * D[iv];
        }
        fft128(xr, xi, twc, tws, lane);
#pragma unroll
        for (int r = 0; r < 4; r++) {
            int n = r * 32 + lane;
            sZr[n * 33 + p] = xr[r];
            sZi[n * 33 + p] = xi[r];
        }
    }
    __syncthreads();
    // unpack: X_u[f] = (Z[f]+conj(Z[g]))/2 ; X_v[f] = (Z[f]-conj(Z[g]))/(2i)
    for (int i = tid; i < NF * KIN; i += 512) {
        int f = i >> 6, j = i & 63;
        int p = j >> 1, v = j & 1;
        int g = (128 - f) & 127;
        int sf = __brev((unsigned)f) >> 25;
        int sg = __brev((unsigned)g) >> 25;
        float zr1 = sZr[sf * 33 + p], zi1 = sZi[sf * 33 + p];
        float zr2 = sZr[sg * 33 + p], zi2 = sZi[sg * 33 + p];
        float outr, outi;
        if (v == 0) { outr = 0.5f * (zr1 + zr2); outi = 0.5f * (zi1 - zi2); }
        else        { outr = 0.5f * (zi1 + zi2); outi = 0.5f * (zr2 - zr1); }
        g_Xre[f][b * 64 + j] = outr;
        g_Xim[f][b * 64 + j] = outi;
    }
}

// ---------------- K2: 65 per-frequency complex GEMMs, packed f32x2 FMA --------
// CTA = (128-row b-tile, one frequency), 256 threads. Thread (bw, ow) owns
// rows bw*8..bw*8+7 (as 4 packed pairs) x 4 o-columns.
__global__ void __launch_bounds__(256) cgemm_kernel() {
    extern __shared__ float sm[];
    float* sXr = sm;                          // [64][130]  j-major
    float* sXi = sXr + 64 * 130;
    ull*   sWr2 = (ull*)(sXi + 64 * 130);     // [64][64] duplicated (w,w)
    ull*   sWi2 = sWr2 + 4096;
    int f = blockIdx.y, bt = blockIdx.x, tid = threadIdx.x;

    const float* gxr = g_Xre[f] + bt * 8192;
    const float* gxi = g_Xim[f] + bt * 8192;
    for (int i = tid; i < 8192; i += 256) {
        int bl = i >> 6, j = i & 63;
        sXr[j * 130 + bl] = gxr[i];
        sXi[j * 130 + bl] = gxi[i];
    }
    const float* gwr = g_Wre[f];
    const float* gwi = g_Wim[f];
    for (int i = tid; i < 4096; i += 256) {
        float a = gwr[i], b = gwi[i];
        ((float2*)sWr2)[i] = make_float2(a, a);
        ((float2*)sWi2)[i] = make_float2(b, b);
    }
    __syncthreads();

    int ow = tid & 15, bw = tid >> 4;
    ull accR[4][4], accI[4][4];
#pragma unroll
    for (int t = 0; t < 4; t++)
#pragma unroll
        for (int c = 0; c < 4; c++) { accR[t][c] = 0ULL; accI[t][c] = 0ULL; }

    const float* xrb = sXr + bw * 8;
    const float* xib = sXi + bw * 8;
#pragma unroll 4
    for (int j = 0; j < 64; j++) {
        ull wr2[4], wi2[4];
#pragma unroll
        for (int c = 0; c < 4; c++) {
            wr2[c] = sWr2[j * 64 + ow + 16 * c];
            wi2[c] = sWi2[j * 64 + ow + 16 * c];
        }
        ull xr2[4], xi2[4], nxi2[4];
#pragma unroll
        for (int t = 0; t < 4; t++) {
            xr2[t]  = *(const ull*)(xrb + j * 130 + 2 * t);
            xi2[t]  = *(const ull*)(xib + j * 130 + 2 * t);
            nxi2[t] = xi2[t] ^ 0x8000000080000000ULL;   // ALU pipe, off FMA
        }
#pragma unroll
        for (int t = 0; t < 4; t++)
#pragma unroll
            for (int c = 0; c < 4; c++) {
                // Y = X * Wc : Yr = xr*A - xi*B ; Yi = xr*B + xi*A
                FMA2(accR[t][c], xr2[t],  wr2[c], accR[t][c]);
                FMA2(accR[t][c], nxi2[t], wi2[c], accR[t][c]);
                FMA2(accI[t][c], xr2[t],  wi2[c], accI[t][c]);
                FMA2(accI[t][c], xi2[t],  wr2[c], accI[t][c]);
            }
    }
#pragma unroll
    for (int t = 0; t < 4; t++) {
        int b0 = bt * 128 + bw * 8 + 2 * t;
        float2* d0 = (float2*)(g_Y + ((size_t)b0 * NF + f) * 128);
        float2* d1 = (float2*)(g_Y + ((size_t)(b0 + 1) * NF + f) * 128);
#pragma unroll
        for (int c = 0; c < 4; c++) {
            int o = ow + 16 * c;
            float rl, rh, il, ih;
            UNPACK2(rl, rh, accR[t][c]);
            UNPACK2(il, ih, accI[t][c]);
            d0[o] = make_float2(rl, il);
            d1[o] = make_float2(rh, ih);
        }
    }
}

// ---------------- K3: Hermitian IFFT, 2 real output blocks per FFT ------------
// One CTA per batch row, 512 threads. Warp w handles o-pairs (4w,4w+1),(4w+2,4w+3).
// z[k] = Y_o[k] + i*Y_{o+1}[k] with Hermitian extension;
// y_o = Re(ifft z), y_{o+1} = Im(ifft z); ifft z = conj(fft(conj z))/128.
__global__ void __launch_bounds__(512) ifft_kernel(float* __restrict__ out) {
    extern __shared__ float sm[];
    float* sYr = sm;                  // [64][65]
    float* sYi = sYr + 64 * 65;
    float* st  = sYi + 64 * 65;       // [16][256]
    float* twc = st + 16 * 256;
    float* tws = twc + 64;
    int b = blockIdx.x, tid = threadIdx.x;
    if (tid < 64) {
        float ang = -6.2831853071795864769f * (float)tid / 128.0f;
        twc[tid] = cosf(ang);
        tws[tid] = sinf(ang);
    }
    const float2* gy = (const float2*)(g_Y + (size_t)b * (NF * KOUT * 2));
    for (int i = tid; i < NF * KOUT; i += 512) {
        int f = i >> 6, o = i & 63;
        float2 v = gy[i];
        sYr[o * 65 + f] = v.x;
        sYi[o * 65 + f] = v.y;
    }
    __syncthreads();

    int warp = tid >> 5, lane = tid & 31;
    float* stw = st + warp * 256;
    for (int q = 0; q < 2; q++) {
        int o = warp * 4 + q * 2;     // blocks o, o+1
        float zr[4], zi[4];
#pragma unroll
        for (int r = 0; r < 4; r++) {
            int k = r * 32 + lane;
            if (k <= 64) {
                float a  = sYr[o * 65 + k],       bb = sYi[o * 65 + k];
                float c  = sYr[(o + 1) * 65 + k], d  = sYi[(o + 1) * 65 + k];
                zr[r] = a - d;  zi[r] = bb + c;       // z = Y1 + i Y2
            } else {
                int k2 = 128 - k;                      // Hermitian extension
                float a  = sYr[o * 65 + k2],       bb = sYi[o * 65 + k2];
                float c  = sYr[(o + 1) * 65 + k2], d  = sYi[(o + 1) * 65 + k2];
                zr[r] = a + d;  zi[r] = c - bb;
            }
            zi[r] = -zi[r];                            // conj(z)
        }
        fft128(zr, zi, twc, tws, lane);
#pragma unroll
        for (int r = 0; r < 4; r++) {
            int n = r * 32 + lane;
            int tp = __brev((unsigned)n) >> 25;
            stw[tp]       = zr[r] * (1.0f / 128.0f);   // y_o
            stw[128 + tp] = zi[r] * (-1.0f / 128.0f);  // y_{o+1}
        }
        __syncwarp();
        float* dst = out + (size_t)b * DOUT + o * 128;
#pragma unroll
        for (int r = 0; r < 8; r++)
            dst[r * 32 + lane] = stw[r * 32 + lane];
        __syncwarp();
    }
}

// ---------------- launch ------------------------------------------------------
extern "C" void kernel_launch(void* const* d_in, const int* in_sizes, int n_in,
                              void* d_out, int out_size) {
    const float* x = (const float*)d_in[0];   // (4096, 8192)
    const float* W = (const float*)d_in[1];   // (64, 64, 128)
    const float* D = (const float*)d_in[2];   // (8192,)
    float* out = (float*)d_out;               // (4096, 8192)
    (void)in_sizes; (void)n_in; (void)out_size;

    const int smem_x = (2 * 128 * 33 + 128) * 4;                  // 34304 B
    const int smem_g = (2 * 64 * 130) * 4 + 2 * 4096 * 8;         // 132096 B
    const int smem_i = (2 * 64 * 65 + 16 * 256 + 128) * 4;        // 50176 B
    cudaFuncSetAttribute(xfft_kernel,  cudaFuncAttributeMaxDynamicSharedMemorySize, smem_x);
    cudaFuncSetAttribute(cgemm_kernel, cudaFuncAttributeMaxDynamicSharedMemorySize, smem_g);
    cudaFuncSetAttribute(ifft_kernel,  cudaFuncAttributeMaxDynamicSharedMemorySize, smem_i);

    wfft_kernel<<<KOUT * KIN, 128>>>(W);
    xfft_kernel<<<BATCH, 512, smem_x>>>(x, D);
    cgemm_kernel<<<dim3(BATCH / 128, NF), 256, smem_g>>>();
    ifft_kernel<<<BATCH, 512, smem_i>>>(out);
}

// round 7
// speedup vs baseline: 1.2312x; 1.1067x over previous
#include <cuda_runtime.h>
#include <cuda_bf16.h>
#include <cstdint>
#include <cstddef>

typedef unsigned long long ull;

#define BATCH 4096
#define DIN   8192
#define DOUT  8192
#define KIN   64
#define KOUT  64
#define NF    65     // rfft bins of 128

// ---------------- scratch (static device globals; no allocation) -------------
__device__ float g_Xre[NF][BATCH * KIN];             // [f][b*64+j]
__device__ float g_Xim[NF][BATCH * KIN];
__device__ float g_Wre[NF][KIN * KOUT];              // [f][j*64+o] = Re conj(fft W)
__device__ float g_Wim[NF][KIN * KOUT];              // [f][j*64+o] = Im conj(fft W)
__device__ float g_Y[(size_t)BATCH * NF * KOUT * 2]; // [b][f][o][re,im]
// B tiles, plain row-major [n][k] bf16 hi/lo per frequency (128x128 each)
__device__ __align__(16) __nv_bfloat16 g_Bhi[NF][128 * 128];
__device__ __align__(16) __nv_bfloat16 g_Blo[NF][128 * 128];

__device__ __forceinline__ uint32_t smem_to_u32(const void* p) {
    uint32_t a;
    asm("{ .reg .u64 t; cvta.to.shared.u64 t, %1; cvt.u32.u64 %0, t; }"
        : "=r"(a) : "l"(p));
    return a;
}
#define LDMATRIX_X4(r0, r1, r2, r3, addr) \
    asm volatile("ldmatrix.sync.aligned.m8n8.x4.shared.b16 {%0,%1,%2,%3}, [%4];" \
        : "=r"(r0), "=r"(r1), "=r"(r2), "=r"(r3) : "r"(addr))
#define MMA_BF16(c, a, b) \
    asm volatile("mma.sync.aligned.m16n8k16.row.col.f32.bf16.bf16.f32 " \
        "{%0,%1,%2,%3}, {%4,%5,%6,%7}, {%8,%9}, {%0,%1,%2,%3};" \
        : "+f"((c)[0]), "+f"((c)[1]), "+f"((c)[2]), "+f"((c)[3]) \
        : "r"((a)[0]), "r"((a)[1]), "r"((a)[2]), "r"((a)[3]), \
          "r"((b)[0]), "r"((b)[1]))

// ---------------- warp-level 128-pt radix-2 DIF FFT --------------------------
__device__ __forceinline__ void fft128(float xr[4], float xi[4],
                                       const float* __restrict__ twc,
                                       const float* __restrict__ tws,
                                       int lane) {
#pragma unroll
    for (int r = 0; r < 2; r++) {
        int i = r * 32 + lane;
        float ar = xr[r], ai = xi[r], br = xr[r + 2], bi = xi[r + 2];
        xr[r] = ar + br; xi[r] = ai + bi;
        float dr = ar - br, di = ai - bi;
        float c = twc[i], s = tws[i];
        xr[r + 2] = dr * c - di * s;
        xi[r + 2] = dr * s + di * c;
    }
    {
        float c = twc[2 * lane], s = tws[2 * lane];
#pragma unroll
        for (int p = 0; p < 2; p++) {
            int a = 2 * p, bq = 2 * p + 1;
            float ar = xr[a], ai = xi[a], br = xr[bq], bi = xi[bq];
            xr[a] = ar + br; xi[a] = ai + bi;
            float dr = ar - br, di = ai - bi;
            xr[bq] = dr * c - di * s;
            xi[bq] = dr * s + di * c;
        }
    }
#pragma unroll
    for (int h = 16; h >= 1; h >>= 1) {
        int m = (lane & (h - 1)) * (64 / h);
        float c = twc[m], s = tws[m];
        bool upper = (lane & h) != 0;
#pragma unroll
        for (int r = 0; r < 4; r++) {
            float pr = __shfl_xor_sync(0xffffffffu, xr[r], h);
            float pi = __shfl_xor_sync(0xffffffffu, xi[r], h);
            float ur = upper ? pr : xr[r];
            float ui = upper ? pi : xi[r];
            float vr = upper ? xr[r] : pr;
            float vi = upper ? xi[r] : pi;
            if (!upper) { xr[r] = ur + vr; xi[r] = ui + vi; }
            else {
                float dr = ur - vr, di = ui - vi;
                xr[r] = dr * c - di * s;
                xi[r] = dr * s + di * c;
            }
        }
    }
}

// ---------------- K0: conj(FFT) of weight first-rows -------------------------
__global__ void wfft_kernel(const float* __restrict__ W) {
    __shared__ float sw[128];
    __shared__ float tc[128];
    __shared__ float ts[128];
    int oj = blockIdx.x;
    int t = threadIdx.x;
    sw[t] = W[oj * 128 + t];
    float ang = 6.2831853071795864769f * (float)t / 128.0f;  // +sin => conj
    tc[t] = cosf(ang);
    ts[t] = sinf(ang);
    __syncthreads();
    if (t < NF) {
        float ar = 0.f, ai = 0.f;
#pragma unroll 8
        for (int u = 0; u < 128; u++) {
            int p = (t * u) & 127;
            ar = fmaf(sw[u], tc[p], ar);
            ai = fmaf(sw[u], ts[p], ai);
        }
        int o = oj >> 6, j = oj & 63;
        g_Wre[t][j * 64 + o] = ar;
        g_Wim[t][j * 64 + o] = ai;
    }
}

// ---------------- K0b: build B tiles (bf16 hi/lo, row-major [n][k]) ----------
// B[n][k]: n<64 -> Yr rows (o=n): k<64 -> Wr[j=k][o], else -Wi[j][o]
//          n>=64 -> Yi rows:      k<64 -> Wi[j][o],   else  Wr[j][o]
__global__ void bprep_kernel() {
    int f = blockIdx.x;
    for (int i = threadIdx.x; i < 128 * 128; i += blockDim.x) {
        int n = i >> 7, k = i & 127;
        int o = n & 63, j = k & 63;
        float wr = g_Wre[f][j * 64 + o];
        float wi = g_Wim[f][j * 64 + o];
        float v = (n < 64) ? ((k < 64) ? wr : -wi)
                           : ((k < 64) ? wi :  wr);
        __nv_bfloat16 h = __float2bfloat16(v);
        float lo = v - __bfloat162float(h);
        g_Bhi[f][i] = h;
        g_Blo[f][i] = __float2bfloat16(lo);
    }
}

// ---------------- K1: FFT of x blocks, 2 real blocks per complex FFT ----------
__global__ void __launch_bounds__(512) xfft_kernel(const float* __restrict__ x,
                                                   const float* __restrict__ D) {
    extern __shared__ float sm[];
    float* sZr = sm;                 // [128][33]
    float* sZi = sZr + 128 * 33;
    float* twc = sZi + 128 * 33;
    float* tws = twc + 64;
    int b = blockIdx.x, tid = threadIdx.x;
    if (tid < 64) {
        float ang = -6.2831853071795864769f * (float)tid / 128.0f;
        twc[tid] = cosf(ang);
        tws[tid] = sinf(ang);
    }
    __syncthreads();
    int warp = tid >> 5, lane = tid & 31;
    const float* xb = x + (size_t)b * DIN;
    for (int pp = 0; pp < 2; pp++) {
        int p = warp * 2 + pp;
        float xr[4], xi[4];
#pragma unroll
        for (int r = 0; r < 4; r++) {
            int n = r * 32 + lane;
            int iu = (2 * p) * 128 + n;
            int iv = iu + 128;
            xr[r] = xb[iu] * D[iu];
            xi[r] = xb[iv] * D[iv];
        }
        fft128(xr, xi, twc, tws, lane);
#pragma unroll
        for (int r = 0; r < 4; r++) {
            int n = r * 32 + lane;
            sZr[n * 33 + p] = xr[r];
            sZi[n * 33 + p] = xi[r];
        }
    }
    __syncthreads();
    for (int i = tid; i < NF * KIN; i += 512) {
        int f = i >> 6, j = i & 63;
        int p = j >> 1, v = j & 1;
        int g = (128 - f) & 127;
        int sf = __brev((unsigned)f) >> 25;
        int sg = __brev((unsigned)g) >> 25;
        float zr1 = sZr[sf * 33 + p], zi1 = sZi[sf * 33 + p];
        float zr2 = sZr[sg * 33 + p], zi2 = sZi[sg * 33 + p];
        float outr, outi;
        if (v == 0) { outr = 0.5f * (zr1 + zr2); outi = 0.5f * (zi1 - zi2); }
        else        { outr = 0.5f * (zi1 + zi2); outi = 0.5f * (zr2 - zr1); }
        g_Xre[f][b * 64 + j] = outr;
        g_Xim[f][b * 64 + j] = outi;
    }
}

// ---------------- K2: per-frequency GEMM via mma.sync bf16 split-2 ------------
// CTA = (128-row b-tile, one frequency), 256 threads = 8 warps (2M x 4N).
// C[128x128] = A[128x128] x B^T, A = [Xr|Xi] rows, split hi/lo bf16.
// SMEM (272B pitch = conflict-free ldmatrix):
//   Ah @0, Al @34816, Bh @69632, Bl @104448   (total 139264 B)
__global__ void __launch_bounds__(256, 1) cgemm_mma_kernel() {
    extern __shared__ char smem[];
    const int PITCH = 272;
    const uint32_t AL = 34816, BH = 69632, BL = 104448;
    int f = blockIdx.y, bt = blockIdx.x, tid = threadIdx.x;

    // --- stage A: load X fp32, split to bf16 hi/lo ---
    {
        const float2* xr2 = (const float2*)(g_Xre[f] + (size_t)bt * 8192);
        const float2* xi2 = (const float2*)(g_Xim[f] + (size_t)bt * 8192);
        for (int idx = tid; idx < 128 * 32; idx += 256) {
            int m = idx >> 5, kp = idx & 31;
            float2 vr = xr2[idx];
            float2 vi = xi2[idx];
            __nv_bfloat16 h0 = __float2bfloat16(vr.x);
            __nv_bfloat16 h1 = __float2bfloat16(vr.y);
            uint32_t hp = (uint32_t)__bfloat16_as_ushort(h0) |
                          ((uint32_t)__bfloat16_as_ushort(h1) << 16);
            __nv_bfloat16 l0 = __float2bfloat16(vr.x - __bfloat162float(h0));
            __nv_bfloat16 l1 = __float2bfloat16(vr.y - __bfloat162float(h1));
            uint32_t lp = (uint32_t)__bfloat16_as_ushort(l0) |
                          ((uint32_t)__bfloat16_as_ushort(l1) << 16);
            *(uint32_t*)(smem + m * PITCH + kp * 4) = hp;
            *(uint32_t*)(smem + AL + m * PITCH + kp * 4) = lp;
            h0 = __float2bfloat16(vi.x);
            h1 = __float2bfloat16(vi.y);
            hp = (uint32_t)__bfloat16_as_ushort(h0) |
                 ((uint32_t)__bfloat16_as_ushort(h1) << 16);
            l0 = __float2bfloat16(vi.x - __bfloat162float(h0));
            l1 = __float2bfloat16(vi.y - __bfloat162float(h1));
            lp = (uint32_t)__bfloat16_as_ushort(l0) |
                 ((uint32_t)__bfloat16_as_ushort(l1) << 16);
            *(uint32_t*)(smem + m * PITCH + 128 + kp * 4) = hp;
            *(uint32_t*)(smem + AL + m * PITCH + 128 + kp * 4) = lp;
        }
    }
    // --- stage B: copy precomputed tiles into pitched smem ---
    {
        const uint4* bh = (const uint4*)g_Bhi[f];
        const uint4* bl = (const uint4*)g_Blo[f];
        for (int idx = tid; idx < 2048; idx += 256) {
            int n = idx >> 4, c = idx & 15;
            *(uint4*)(smem + BH + n * PITCH + c * 16) = bh[idx];
            *(uint4*)(smem + BL + n * PITCH + c * 16) = bl[idx];
        }
    }
    __syncthreads();

    uint32_t sA = smem_to_u32(smem);
    int lane = tid & 31, wid = tid >> 5;
    int wm = wid >> 2, wn = wid & 3;          // warp tile: M 64 x N 32
    int r = lane & 7, ti = lane >> 3;

    // ldmatrix lane base addresses
    uint32_t aBase = sA + (uint32_t)((wm * 64 + r + 8 * (ti & 1)) * PITCH
                                     + (ti >> 1) * 16);
    uint32_t bBase0 = sA + BH + (uint32_t)((wn * 32 + r + 8 * (ti >> 1)) * PITCH
                                           + (ti & 1) * 16);
    uint32_t bBase1 = bBase0 + 16 * PITCH;

    float acc[4][4][4];
#pragma unroll
    for (int mt = 0; mt < 4; mt++)
#pragma unroll
        for (int nt = 0; nt < 4; nt++)
#pragma unroll
            for (int q = 0; q < 4; q++) acc[mt][nt][q] = 0.f;

#pragma unroll
    for (int s = 0; s < 3; s++) {
        uint32_t aOff = (s == 2) ? AL : 0;          // s2: Al x Bh
        uint32_t bOff = (s == 1) ? (BL - BH) : 0;   // s1: Ah x Bl
#pragma unroll
        for (int ks = 0; ks < 8; ks++) {
            uint32_t kadd = ks * 32;
            uint32_t af[4][4];
#pragma unroll
            for (int mt = 0; mt < 4; mt++)
                LDMATRIX_X4(af[mt][0], af[mt][1], af[mt][2], af[mt][3],
                            aBase + aOff + mt * 16 * PITCH + kadd);
            uint32_t bf[4][2];
            LDMATRIX_X4(bf[0][0], bf[0][1], bf[1][0], bf[1][1],
                        bBase0 + bOff + kadd);
            LDMATRIX_X4(bf[2][0], bf[2][1], bf[3][0], bf[3][1],
                        bBase1 + bOff + kadd);
#pragma unroll
            for (int mt = 0; mt < 4; mt++)
#pragma unroll
                for (int nt = 0; nt < 4; nt++)
                    MMA_BF16(acc[mt][nt], af[mt], bf[nt]);
        }
    }

    // --- epilogue: scatter into g_Y[b][f][o][re,im] ---
    int g = lane >> 2, tg = lane & 3;
#pragma unroll
    for (int mt = 0; mt < 4; mt++) {
        int brow = bt * 128 + wm * 64 + mt * 16 + g;
        float* base0 = g_Y + ((size_t)brow * NF + f) * 128;
        float* base1 = g_Y + ((size_t)(brow + 8) * NF + f) * 128;
#pragma unroll
        for (int nt = 0; nt < 4; nt++) {
            int n = wn * 32 + nt * 8 + 2 * tg;
            int o = n & 63, comp = n >> 6;
            int d = o * 2 + comp;
            base0[d]     = acc[mt][nt][0];
            base0[d + 2] = acc[mt][nt][1];
            base1[d]     = acc[mt][nt][2];
            base1[d + 2] = acc[mt][nt][3];
        }
    }
}

// ---------------- K3: Hermitian IFFT, 2 real output blocks per FFT ------------
__global__ void __launch_bounds__(512) ifft_kernel(float* __restrict__ out) {
    extern __shared__ float sm[];
    float* sYr = sm;                  // [64][65]
    float* sYi = sYr + 64 * 65;
    float* st  = sYi + 64 * 65;       // [16][256]
    float* twc = st + 16 * 256;
    float* tws = twc + 64;
    int b = blockIdx.x, tid = threadIdx.x;
    if (tid < 64) {
        float ang = -6.2831853071795864769f * (float)tid / 128.0f;
        twc[tid] = cosf(ang);
        tws[tid] = sinf(ang);
    }
    const float2* gy = (const float2*)(g_Y + (size_t)b * (NF * KOUT * 2));
    for (int i = tid; i < NF * KOUT; i += 512) {
        int f = i >> 6, o = i & 63;
        float2 v = gy[i];
        sYr[o * 65 + f] = v.x;
        sYi[o * 65 + f] = v.y;
    }
    __syncthreads();

    int warp = tid >> 5, lane = tid & 31;
    float* stw = st + warp * 256;
    for (int q = 0; q < 2; q++) {
        int o = warp * 4 + q * 2;
        float zr[4], zi[4];
#pragma unroll
        for (int r = 0; r < 4; r++) {
            int k = r * 32 + lane;
            if (k <= 64) {
                float a  = sYr[o * 65 + k],       bb = sYi[o * 65 + k];
                float c  = sYr[(o + 1) * 65 + k], d  = sYi[(o + 1) * 65 + k];
                zr[r] = a - d;  zi[r] = bb + c;
            } else {
                int k2 = 128 - k;
                float a  = sYr[o * 65 + k2],       bb = sYi[o * 65 + k2];
                float c  = sYr[(o + 1) * 65 + k2], d  = sYi[(o + 1) * 65 + k2];
                zr[r] = a + d;  zi[r] = c - bb;
            }
            zi[r] = -zi[r];
        }
        fft128(zr, zi, twc, tws, lane);
#pragma unroll
        for (int r = 0; r < 4; r++) {
            int n = r * 32 + lane;
            int tp = __brev((unsigned)n) >> 25;
            stw[tp]       = zr[r] * (1.0f / 128.0f);
            stw[128 + tp] = zi[r] * (-1.0f / 128.0f);
        }
        __syncwarp();
        float* dst = out + (size_t)b * DOUT + o * 128;
#pragma unroll
        for (int r = 0; r < 8; r++)
            dst[r * 32 + lane] = stw[r * 32 + lane];
        __syncwarp();
    }
}

// ---------------- launch ------------------------------------------------------
extern "C" void kernel_launch(void* const* d_in, const int* in_sizes, int n_in,
                              void* d_out, int out_size) {
    const float* x = (const float*)d_in[0];   // (4096, 8192)
    const float* W = (const float*)d_in[1];   // (64, 64, 128)
    const float* D = (const float*)d_in[2];   // (8192,)
    float* out = (float*)d_out;               // (4096, 8192)
    (void)in_sizes; (void)n_in; (void)out_size;

    const int smem_x = (2 * 128 * 33 + 128) * 4;                  // 34304 B
    const int smem_g = 139264;                                    // A+B hi/lo tiles
    const int smem_i = (2 * 64 * 65 + 16 * 256 + 128) * 4;        // 50176 B
    cudaFuncSetAttribute(xfft_kernel,      cudaFuncAttributeMaxDynamicSharedMemorySize, smem_x);
    cudaFuncSetAttribute(cgemm_mma_kernel, cudaFuncAttributeMaxDynamicSharedMemorySize, smem_g);
    cudaFuncSetAttribute(ifft_kernel,      cudaFuncAttributeMaxDynamicSharedMemorySize, smem_i);

    wfft_kernel<<<KOUT * KIN, 128>>>(W);
    bprep_kernel<<<NF, 256>>>();
    xfft_kernel<<<BATCH, 512, smem_x>>>(x, D);
    cgemm_mma_kernel<<<dim3(BATCH / 128, NF), 256, smem_g>>>();
    ifft_kernel<<<BATCH, 512, smem_i>>>(out);
}

// round 9
// speedup vs baseline: 1.4039x; 1.1402x over previous
#include <cuda_runtime.h>
#include <cuda_bf16.h>
#include <cstdint>
#include <cstddef>

typedef unsigned long long ull;

#define BATCH 4096
#define DIN   8192
#define DOUT  8192
#define KIN   64
#define KOUT  64
#define NF    65     // rfft bins of 128

// ---------------- scratch (static device globals; no allocation) -------------
__device__ float g_Xre[NF][BATCH * KIN];             // [f][b*64+j]
__device__ float g_Xim[NF][BATCH * KIN];
__device__ float g_Wre[NF][KIN * KOUT];              // [f][j*64+o] = Re conj(fft W)
__device__ float g_Wim[NF][KIN * KOUT];              // [f][j*64+o] = Im conj(fft W)
__device__ float g_Y[(size_t)BATCH * NF * KOUT * 2]; // [b][f][o][re,im]
// B tiles, plain row-major [n][k] bf16 hi/lo per frequency (128x128 each)
__device__ __align__(16) __nv_bfloat16 g_Bhi[NF][128 * 128];
__device__ __align__(16) __nv_bfloat16 g_Blo[NF][128 * 128];

__device__ __forceinline__ uint32_t smem_to_u32(const void* p) {
    uint32_t a;
    asm("{ .reg .u64 t; cvta.to.shared.u64 t, %1; cvt.u32.u64 %0, t; }"
        : "=r"(a) : "l"(p));
    return a;
}
#define LDMATRIX_X4(r0, r1, r2, r3, addr) \
    asm volatile("ldmatrix.sync.aligned.m8n8.x4.shared.b16 {%0,%1,%2,%3}, [%4];" \
        : "=r"(r0), "=r"(r1), "=r"(r2), "=r"(r3) : "r"(addr))
#define MMA_BF16(c, a, b) \
    asm volatile("mma.sync.aligned.m16n8k16.row.col.f32.bf16.bf16.f32 " \
        "{%0,%1,%2,%3}, {%4,%5,%6,%7}, {%8,%9}, {%0,%1,%2,%3};" \
        : "+f"((c)[0]), "+f"((c)[1]), "+f"((c)[2]), "+f"((c)[3]) \
        : "r"((a)[0]), "r"((a)[1]), "r"((a)[2]), "r"((a)[3]), \
          "r"((b)[0]), "r"((b)[1]))

// ---------------- warp-level 128-pt radix-2 DIF FFT --------------------------
__device__ __forceinline__ void fft128(float xr[4], float xi[4],
                                       const float* __restrict__ twc,
                                       const float* __restrict__ tws,
                                       int lane) {
#pragma unroll
    for (int r = 0; r < 2; r++) {
        int i = r * 32 + lane;
        float ar = xr[r], ai = xi[r], br = xr[r + 2], bi = xi[r + 2];
        xr[r] = ar + br; xi[r] = ai + bi;
        float dr = ar - br, di = ai - bi;
        float c = twc[i], s = tws[i];
        xr[r + 2] = dr * c - di * s;
        xi[r + 2] = dr * s + di * c;
    }
    {
        float c = twc[2 * lane], s = tws[2 * lane];
#pragma unroll
        for (int p = 0; p < 2; p++) {
            int a = 2 * p, bq = 2 * p + 1;
            float ar = xr[a], ai = xi[a], br = xr[bq], bi = xi[bq];
            xr[a] = ar + br; xi[a] = ai + bi;
            float dr = ar - br, di = ai - bi;
            xr[bq] = dr * c - di * s;
            xi[bq] = dr * s + di * c;
        }
    }
#pragma unroll
    for (int h = 16; h >= 1; h >>= 1) {
        int m = (lane & (h - 1)) * (64 / h);
        float c = twc[m], s = tws[m];
        bool upper = (lane & h) != 0;
#pragma unroll
        for (int r = 0; r < 4; r++) {
            float pr = __shfl_xor_sync(0xffffffffu, xr[r], h);
            float pi = __shfl_xor_sync(0xffffffffu, xi[r], h);
            float ur = upper ? pr : xr[r];
            float ui = upper ? pi : xi[r];
            float vr = upper ? xr[r] : pr;
            float vi = upper ? xi[r] : pi;
            if (!upper) { xr[r] = ur + vr; xi[r] = ui + vi; }
            else {
                float dr = ur - vr, di = ui - vi;
                xr[r] = dr * c - di * s;
                xi[r] = dr * s + di * c;
            }
        }
    }
}

// ---------------- K0: conj(FFT) of weight first-rows -------------------------
__global__ void wfft_kernel(const float* __restrict__ W) {
    __shared__ float sw[128];
    __shared__ float tc[128];
    __shared__ float ts[128];
    int oj = blockIdx.x;
    int t = threadIdx.x;
    sw[t] = W[oj * 128 + t];
    float ang = 6.2831853071795864769f * (float)t / 128.0f;  // +sin => conj
    tc[t] = cosf(ang);
    ts[t] = sinf(ang);
    __syncthreads();
    if (t < NF) {
        float ar = 0.f, ai = 0.f;
#pragma unroll 8
        for (int u = 0; u < 128; u++) {
            int p = (t * u) & 127;
            ar = fmaf(sw[u], tc[p], ar);
            ai = fmaf(sw[u], ts[p], ai);
        }
        int o = oj >> 6, j = oj & 63;
        g_Wre[t][j * 64 + o] = ar;
        g_Wim[t][j * 64 + o] = ai;
    }
}

// ---------------- K0b: build B tiles (bf16 hi/lo, row-major [n][k]) ----------
// B[n][k]: n<64 -> Yr rows (o=n): k<64 -> Wr[j=k][o], else -Wi[j][o]
//          n>=64 -> Yi rows:      k<64 -> Wi[j][o],   else  Wr[j][o]
__global__ void bprep_kernel() {
    int f = blockIdx.x;
    for (int i = threadIdx.x; i < 128 * 128; i += blockDim.x) {
        int n = i >> 7, k = i & 127;
        int o = n & 63, j = k & 63;
        float wr = g_Wre[f][j * 64 + o];
        float wi = g_Wim[f][j * 64 + o];
        float v = (n < 64) ? ((k < 64) ? wr : -wi)
                           : ((k < 64) ? wi :  wr);
        __nv_bfloat16 h = __float2bfloat16(v);
        float lo = v - __bfloat162float(h);
        g_Bhi[f][i] = h;
        g_Blo[f][i] = __float2bfloat16(lo);
    }
}

// ---------------- K1: FFT of x blocks, 2 real blocks per complex FFT ----------
__global__ void __launch_bounds__(512) xfft_kernel(const float* __restrict__ x,
                                                   const float* __restrict__ D) {
    extern __shared__ float sm[];
    float* sZr = sm;                 // [128][33]
    float* sZi = sZr + 128 * 33;
    float* twc = sZi + 128 * 33;
    float* tws = twc + 64;
    int b = blockIdx.x, tid = threadIdx.x;
    if (tid < 64) {
        float ang = -6.2831853071795864769f * (float)tid / 128.0f;
        twc[tid] = cosf(ang);
        tws[tid] = sinf(ang);
    }
    __syncthreads();
    int warp = tid >> 5, lane = tid & 31;
    const float* xb = x + (size_t)b * DIN;
    for (int pp = 0; pp < 2; pp++) {
        int p = warp * 2 + pp;
        float xr[4], xi[4];
#pragma unroll
        for (int r = 0; r < 4; r++) {
            int n = r * 32 + lane;
            int iu = (2 * p) * 128 + n;
            int iv = iu + 128;
            xr[r] = xb[iu] * D[iu];
            xi[r] = xb[iv] * D[iv];
        }
        fft128(xr, xi, twc, tws, lane);
#pragma unroll
        for (int r = 0; r < 4; r++) {
            int n = r * 32 + lane;
            sZr[n * 33 + p] = xr[r];
            sZi[n * 33 + p] = xi[r];
        }
    }
    __syncthreads();
    for (int i = tid; i < NF * KIN; i += 512) {
        int f = i >> 6, j = i & 63;
        int p = j >> 1, v = j & 1;
        int g = (128 - f) & 127;
        int sf = __brev((unsigned)f) >> 25;
        int sg = __brev((unsigned)g) >> 25;
        float zr1 = sZr[sf * 33 + p], zi1 = sZi[sf * 33 + p];
        float zr2 = sZr[sg * 33 + p], zi2 = sZi[sg * 33 + p];
        float outr, outi;
        if (v == 0) { outr = 0.5f * (zr1 + zr2); outi = 0.5f * (zi1 - zi2); }
        else        { outr = 0.5f * (zi1 + zi2); outi = 0.5f * (zr2 - zr1); }
        g_Xre[f][b * 64 + j] = outr;
        g_Xim[f][b * 64 + j] = outi;
    }
}

// ---------------- K2: per-frequency GEMM via mma.sync bf16 split-2 ------------
// CTA = (128-row b-tile, one frequency), 512 threads = 16 warps (4M x 4N).
// Warp tile 32x32 -> acc = 32 floats/thread (no spills).
// SMEM (272B pitch = conflict-free ldmatrix):
//   Ah @0, Al @34816, Bh @69632, Bl @104448   (total 139264 B)
__global__ void __launch_bounds__(512, 1) cgemm_mma_kernel() {
    extern __shared__ char smem[];
    const int PITCH = 272;
    const uint32_t AL = 34816, BH = 69632, BL = 104448;
    int f = blockIdx.y, bt = blockIdx.x, tid = threadIdx.x;

    // --- stage A: load X fp32, split to bf16 hi/lo ---
    {
        const float2* xr2 = (const float2*)(g_Xre[f] + (size_t)bt * 8192);
        const float2* xi2 = (const float2*)(g_Xim[f] + (size_t)bt * 8192);
        for (int idx = tid; idx < 128 * 32; idx += 512) {
            int m = idx >> 5, kp = idx & 31;
            float2 vr = xr2[idx];
            float2 vi = xi2[idx];
            __nv_bfloat16 h0 = __float2bfloat16(vr.x);
            __nv_bfloat16 h1 = __float2bfloat16(vr.y);
            uint32_t hp = (uint32_t)__bfloat16_as_ushort(h0) |
                          ((uint32_t)__bfloat16_as_ushort(h1) << 16);
            __nv_bfloat16 l0 = __float2bfloat16(vr.x - __bfloat162float(h0));
            __nv_bfloat16 l1 = __float2bfloat16(vr.y - __bfloat162float(h1));
            uint32_t lp = (uint32_t)__bfloat16_as_ushort(l0) |
                          ((uint32_t)__bfloat16_as_ushort(l1) << 16);
            *(uint32_t*)(smem + m * PITCH + kp * 4) = hp;
            *(uint32_t*)(smem + AL + m * PITCH + kp * 4) = lp;
            h0 = __float2bfloat16(vi.x);
            h1 = __float2bfloat16(vi.y);
            hp = (uint32_t)__bfloat16_as_ushort(h0) |
                 ((uint32_t)__bfloat16_as_ushort(h1) << 16);
            l0 = __float2bfloat16(vi.x - __bfloat162float(h0));
            l1 = __float2bfloat16(vi.y - __bfloat162float(h1));
            lp = (uint32_t)__bfloat16_as_ushort(l0) |
                 ((uint32_t)__bfloat16_as_ushort(l1) << 16);
            *(uint32_t*)(smem + m * PITCH + 128 + kp * 4) = hp;
            *(uint32_t*)(smem + AL + m * PITCH + 128 + kp * 4) = lp;
        }
    }
    // --- stage B: copy precomputed tiles into pitched smem ---
    {
        const uint4* bh = (const uint4*)g_Bhi[f];
        const uint4* bl = (const uint4*)g_Blo[f];
        for (int idx = tid; idx < 2048; idx += 512) {
            int n = idx >> 4, c = idx & 15;
            *(uint4*)(smem + BH + n * PITCH + c * 16) = bh[idx];
            *(uint4*)(smem + BL + n * PITCH + c * 16) = bl[idx];
        }
    }
    __syncthreads();

    uint32_t sA = smem_to_u32(smem);
    int lane = tid & 31, wid = tid >> 5;
    int wm = wid >> 2, wn = wid & 3;          // warp tile: M 32 x N 32
    int r = lane & 7, ti = lane >> 3;

    // ldmatrix lane base addresses
    uint32_t aBase = sA + (uint32_t)((wm * 32 + r + 8 * (ti & 1)) * PITCH
                                     + (ti >> 1) * 16);
    uint32_t bBase0 = sA + BH + (uint32_t)((wn * 32 + r + 8 * (ti >> 1)) * PITCH
                                           + (ti & 1) * 16);
    uint32_t bBase1 = bBase0 + 16 * PITCH;

    float acc[2][4][4];
#pragma unroll
    for (int mt = 0; mt < 2; mt++)
#pragma unroll
        for (int nt = 0; nt < 4; nt++)
#pragma unroll
            for (int q = 0; q < 4; q++) acc[mt][nt][q] = 0.f;

#pragma unroll
    for (int s = 0; s < 3; s++) {
        uint32_t aOff = (s == 2) ? AL : 0;          // s2: Al x Bh
        uint32_t bOff = (s == 1) ? (BL - BH) : 0;   // s1: Ah x Bl
#pragma unroll
        for (int ks = 0; ks < 8; ks++) {
            uint32_t kadd = ks * 32;
            uint32_t af[2][4];
#pragma unroll
            for (int mt = 0; mt < 2; mt++)
                LDMATRIX_X4(af[mt][0], af[mt][1], af[mt][2], af[mt][3],
                            aBase + aOff + mt * 16 * PITCH + kadd);
            uint32_t bf[4][2];
            LDMATRIX_X4(bf[0][0], bf[0][1], bf[1][0], bf[1][1],
                        bBase0 + bOff + kadd);
            LDMATRIX_X4(bf[2][0], bf[2][1], bf[3][0], bf[3][1],
                        bBase1 + bOff + kadd);
#pragma unroll
            for (int mt = 0; mt < 2; mt++)
#pragma unroll
                for (int nt = 0; nt < 4; nt++)
                    MMA_BF16(acc[mt][nt], af[mt], bf[nt]);
        }
    }

    // --- epilogue: scatter into g_Y[b][f][o][re,im] ---
    int g = lane >> 2, tg = lane & 3;
#pragma unroll
    for (int mt = 0; mt < 2; mt++) {
        int brow = bt * 128 + wm * 32 + mt * 16 + g;
        float* base0 = g_Y + ((size_t)brow * NF + f) * 128;
        float* base1 = g_Y + ((size_t)(brow + 8) * NF + f) * 128;
#pragma unroll
        for (int nt = 0; nt < 4; nt++) {
            int n = wn * 32 + nt * 8 + 2 * tg;
            int o = n & 63, comp = n >> 6;
            int d = o * 2 + comp;
            base0[d]     = acc[mt][nt][0];
            base0[d + 2] = acc[mt][nt][1];
            base1[d]     = acc[mt][nt][2];
            base1[d + 2] = acc[mt][nt][3];
        }
    }
}

// ---------------- K3: Hermitian IFFT, 2 real output blocks per FFT ------------
__global__ void __launch_bounds__(512) ifft_kernel(float* __restrict__ out) {
    extern __shared__ float sm[];
    float* sYr = sm;                  // [64][65]
    float* sYi = sYr + 64 * 65;
    float* st  = sYi + 64 * 65;       // [16][256]
    float* twc = st + 16 * 256;
    float* tws = twc + 64;
    int b = blockIdx.x, tid = threadIdx.x;
    if (tid < 64) {
        float ang = -6.2831853071795864769f * (float)tid / 128.0f;
        twc[tid] = cosf(ang);
        tws[tid] = sinf(ang);
    }
    const float2* gy = (const float2*)(g_Y + (size_t)b * (NF * KOUT * 2));
    for (int i = tid; i < NF * KOUT; i += 512) {
        int f = i >> 6, o = i & 63;
        float2 v = gy[i];
        sYr[o * 65 + f] = v.x;
        sYi[o * 65 + f] = v.y;
    }
    __syncthreads();

    int warp = tid >> 5, lane = tid & 31;
    float* stw = st + warp * 256;
    for (int q = 0; q < 2; q++) {
        int o = warp * 4 + q * 2;
        float zr[4], zi[4];
#pragma unroll
        for (int r = 0; r < 4; r++) {
            int k = r * 32 + lane;
            if (k <= 64) {
                float a  = sYr[o * 65 + k],       bb = sYi[o * 65 + k];
                float c  = sYr[(o + 1) * 65 + k], d  = sYi[(o + 1) * 65 + k];
                zr[r] = a - d;  zi[r] = bb + c;
            } else {
                int k2 = 128 - k;
                float a  = sYr[o * 65 + k2],       bb = sYi[o * 65 + k2];
                float c  = sYr[(o + 1) * 65 + k2], d  = sYi[(o + 1) * 65 + k2];
                zr[r] = a + d;  zi[r] = c - bb;
            }
            zi[r] = -zi[r];
        }
        fft128(zr, zi, twc, tws, lane);
#pragma unroll
        for (int r = 0; r < 4; r++) {
            int n = r * 32 + lane;
            int tp = __brev((unsigned)n) >> 25;
            stw[tp]       = zr[r] * (1.0f / 128.0f);
            stw[128 + tp] = zi[r] * (-1.0f / 128.0f);
        }
        __syncwarp();
        float* dst = out + (size_t)b * DOUT + o * 128;
#pragma unroll
        for (int r = 0; r < 8; r++)
            dst[r * 32 + lane] = stw[r * 32 + lane];
        __syncwarp();
    }
}

// ---------------- launch ------------------------------------------------------
extern "C" void kernel_launch(void* const* d_in, const int* in_sizes, int n_in,
                              void* d_out, int out_size) {
    const float* x = (const float*)d_in[0];   // (4096, 8192)
    const float* W = (const float*)d_in[1];   // (64, 64, 128)
    const float* D = (const float*)d_in[2];   // (8192,)
    float* out = (float*)d_out;               // (4096, 8192)
    (void)in_sizes; (void)n_in; (void)out_size;

    const int smem_x = (2 * 128 * 33 + 128) * 4;                  // 34304 B
    const int smem_g = 139264;                                    // A+B hi/lo tiles
    const int smem_i = (2 * 64 * 65 + 16 * 256 + 128) * 4;        // 50176 B
    cudaFuncSetAttribute(xfft_kernel,      cudaFuncAttributeMaxDynamicSharedMemorySize, smem_x);
    cudaFuncSetAttribute(cgemm_mma_kernel, cudaFuncAttributeMaxDynamicSharedMemorySize, smem_g);
    cudaFuncSetAttribute(ifft_kernel,      cudaFuncAttributeMaxDynamicSharedMemorySize, smem_i);

    wfft_kernel<<<KOUT * KIN, 128>>>(W);
    bprep_kernel<<<NF, 256>>>();
    xfft_kernel<<<BATCH, 512, smem_x>>>(x, D);
    cgemm_mma_kernel<<<dim3(BATCH / 128, NF), 512, smem_g>>>();
    ifft_kernel<<<BATCH, 512, smem_i>>>(out);
}